// round 2
// baseline (speedup 1.0000x reference)
#include <cuda_runtime.h>
#include <math.h>

// ---------------------------------------------------------------------------
// casConv2d: B=1, C=128, H=W=32, OC=128, K=3, pad=1 -> OH=OW=32, L=1024
// ckk = 1152, ARRAY_SIZE=32 -> reference pads a FULL zero chunk in front
// (contributes exactly 0 after fake-quant), leaving 36 real chunks:
//   chunk j (0..35) = ckk indices [32j, 32j+32), idx = c*9 + kh*3 + kw
//
// Kernel 1: per-chunk partial sums -> g_part[j][l][oc]   (fp32, 18.9 MB, L2)
// Kernel 2: totals(+bias) -> max/min over oc -> scale/zp -> fake-quant ->
//           sum over chunks -> out[oc][l]
// ---------------------------------------------------------------------------

#define WSTR 130  // w_s row stride (floats): 2-way STS conflict, 8B aligned

typedef unsigned long long u64;

__device__ float g_part[36u * 1024u * 128u];  // [j][l][oc]

__device__ __forceinline__ u64 fma2(u64 a, u64 b, u64 c) {
    u64 d;
    asm("fma.rn.f32x2 %0, %1, %2, %3;" : "=l"(d) : "l"(a), "l"(b), "l"(c));
    return d;
}

__device__ __forceinline__ u64 bcast2(float v) {
    u64 d;
    unsigned u = __float_as_uint(v);
    asm("mov.b64 %0, {%1, %1};" : "=l"(d) : "r"(u));
    return d;
}

__device__ __forceinline__ float2 unpack2(u64 v) {
    float2 f;
    asm("mov.b64 {%0, %1}, %2;" : "=f"(f.x), "=f"(f.y) : "l"(v));
    return f;
}

// ---------------------------------------------------------------------------
// Kernel 1: chunk partial sums.
// grid = (8 l-tiles, 36 chunks), block = 256 threads.
// Block tile: 128 oc x 128 l (4 output rows x 32 cols).
// Thread tile: 8 oc x 8 l, accumulated as 4 oc-pairs in f32x2 registers.
// ---------------------------------------------------------------------------
__global__ void __launch_bounds__(256, 2)
k_partials(const float* __restrict__ x, const float* __restrict__ w) {
    __shared__ float x_s[5 * 6 * 34];     // [c_rel][row(6)][col(34)], zero-padded halo
    __shared__ float w_s[32 * WSTR];      // [t][oc], padded stride

    const int j    = blockIdx.y;
    const int oh0  = blockIdx.x * 4;      // first output row of this tile
    const int base = 32 * j;              // first ckk index of this chunk
    const int cmin = base / 9;            // first channel touched (<=5 channels)
    const int tid  = threadIdx.x;

    // --- load x halo: channels cmin..cmin+4, rows oh0-1..oh0+4, cols -1..32
    for (int e = tid; e < 5 * 6 * 34; e += 256) {
        int cr  = e / 204;
        int rem = e - cr * 204;
        int rr  = rem / 34;
        int cc  = rem - rr * 34;
        int c   = cmin + cr;
        int gh  = oh0 - 1 + rr;
        int gw  = cc - 1;
        float v = 0.0f;
        if (c < 128 && (unsigned)gh < 32u && (unsigned)gw < 32u)
            v = x[(c << 10) + (gh << 5) + gw];
        x_s[e] = v;
    }
    // --- load w: w_s[m][oc] = w[oc*1152 + base + m]  (coalesced global reads)
    for (int e = tid; e < 4096; e += 256) {
        int oc = e >> 5;
        int m  = e & 31;
        w_s[m * WSTR + oc] = w[oc * 1152 + base + m];
    }
    __syncthreads();

    const int lcol = tid & 15;            // 16 l-groups of 8
    const int oc0  = (tid >> 4) << 3;     // 16 oc-groups of 8
    const int lrow = lcol >> 2;           // output row within tile (0..3)
    const int colb = (lcol & 3) << 3;     // first output col (0,8,16,24)

    u64 acc[4][8];                        // [oc-pair][l] f32x2 accumulators
#pragma unroll
    for (int p = 0; p < 4; ++p)
#pragma unroll
        for (int i = 0; i < 8; ++i) acc[p][i] = 0ull;

#pragma unroll
    for (int t = 0; t < 32; ++t) {
        const int idx = base + t;         // uniform across block
        const int c   = idx / 9;
        const int r9  = idx - c * 9;
        const int kh  = r9 / 3;
        const int kw  = r9 - kh * 3;
        const float* xr = &x_s[(c - cmin) * 204 + (lrow + kh) * 34 + colb + kw];
        const u64*   wr = (const u64*)&w_s[t * WSTR + oc0];
        const u64 w0 = wr[0], w1 = wr[1], w2 = wr[2], w3 = wr[3];
#pragma unroll
        for (int i = 0; i < 8; ++i) {
            const u64 xx = bcast2(xr[i]);
            acc[0][i] = fma2(w0, xx, acc[0][i]);
            acc[1][i] = fma2(w1, xx, acc[1][i]);
            acc[2][i] = fma2(w2, xx, acc[2][i]);
            acc[3][i] = fma2(w3, xx, acc[3][i]);
        }
    }

    // --- store partials: g_part[j][l][oc], 8 oc contiguous -> 2x STG.128 per l
    float* outp = g_part + ((size_t)j * 1024 + (size_t)(oh0 << 5)) * 128;
#pragma unroll
    for (int i = 0; i < 8; ++i) {
        const int l = (lcol << 3) + i;    // l within tile
        float2 a0 = unpack2(acc[0][i]);
        float2 a1 = unpack2(acc[1][i]);
        float2 a2 = unpack2(acc[2][i]);
        float2 a3 = unpack2(acc[3][i]);
        *(float4*)&outp[l * 128 + oc0]     = make_float4(a0.x, a0.y, a1.x, a1.y);
        *(float4*)&outp[l * 128 + oc0 + 4] = make_float4(a2.x, a2.y, a3.x, a3.y);
    }
}

// ---------------------------------------------------------------------------
// Kernel 2: fused totals -> scale/zp -> fake-quant -> chunk sum.
// grid = 256 blocks, block = 512 threads = 4 l x 128 oc.
// Each thread caches its 36 partials in registers (single 19 MB L2 pass).
// ---------------------------------------------------------------------------
__global__ void __launch_bounds__(512)
k_quant(const float* __restrict__ bias, float* __restrict__ out) {
    const int tid = threadIdx.x;
    const int oc  = tid & 127;
    const int li  = tid >> 7;                       // 0..3
    const int l   = (blockIdx.x << 2) + li;

    float p[36];
#pragma unroll
    for (int jj = 0; jj < 36; ++jj)
        p[jj] = g_part[((size_t)jj * 1024 + l) * 128 + oc];

    float tot = bias[oc];
#pragma unroll
    for (int jj = 0; jj < 36; ++jj) tot += p[jj];

    // max/min over 128 oc for this l: warp shfl (32 oc) + smem across 4 warps
    float mx = tot, mn = tot;
#pragma unroll
    for (int s = 16; s > 0; s >>= 1) {
        mx = fmaxf(mx, __shfl_xor_sync(0xffffffffu, mx, s));
        mn = fminf(mn, __shfl_xor_sync(0xffffffffu, mn, s));
    }
    __shared__ float smx[4][4], smn[4][4], ssc[4], szp[4];
    const int wrp = (tid >> 5) & 3;
    if ((tid & 31) == 0) { smx[li][wrp] = mx; smn[li][wrp] = mn; }
    __syncthreads();
    if (tid < 4) {
        float M = smx[tid][0], m2 = smn[tid][0];
#pragma unroll
        for (int k = 1; k < 4; ++k) {
            M  = fmaxf(M,  smx[tid][k]);
            m2 = fminf(m2, smn[tid][k]);
        }
        float sc = (M - m2) / 255.0f;               // scale = (mx-mn)/qmax
        float z  = -m2 / sc;                        // may be inf/nan if sc==0
        z = fminf(fmaxf(z, 0.0f), 255.0f);          // clip (nan -> 0 via fmaxf)
        if (isnan(z)) z = 0.0f;
        z = truncf(z);                              // .int() truncation
        ssc[tid] = sc;
        szp[tid] = z;
    }
    __syncthreads();
    const float sc = ssc[li];
    const float zp = szp[li];

    float o = 0.0f;
#pragma unroll
    for (int jj = 0; jj < 36; ++jj) {
        float q = rintf(p[jj] / sc) + zp;           // jnp.round = half-to-even
        q = fminf(fmaxf(q, 0.0f), 255.0f);
        o += (q - zp) * sc;                         // deq (== quant_accu fwd)
    }
    out[(oc << 10) + l] = o;                        // (B,OC,OH,OW) row-major
}

// ---------------------------------------------------------------------------
extern "C" void kernel_launch(void* const* d_in, const int* in_sizes, int n_in,
                              void* d_out, int out_size) {
    const float *x = nullptr, *w = nullptr, *b = nullptr;
    for (int i = 0; i < n_in; ++i) {
        if      (in_sizes[i] == 131072) x = (const float*)d_in[i];  // 128*32*32
        else if (in_sizes[i] == 147456) w = (const float*)d_in[i];  // 128*128*9
        else if (in_sizes[i] == 128)    b = (const float*)d_in[i];
    }
    k_partials<<<dim3(8, 36), 256>>>(x, w);
    k_quant<<<256, 512>>>(b, (float*)d_out);
}

// round 3
// speedup vs baseline: 1.0418x; 1.0418x over previous
#include <cuda_runtime.h>
#include <math.h>

// ---------------------------------------------------------------------------
// casConv2d: B=1, C=128, H=W=32, OC=128, K=3, pad=1 -> OH=OW=32, L=1024
// ckk = 1152, ARRAY_SIZE=32 -> reference's front-pad chunk is all-zero
// (contributes exactly 0 after fake-quant), leaving 36 real chunks:
//   chunk j (0..35) = ckk indices [32j, 32j+32), idx = c*9 + kh*3 + kw
//
// Kernel 1: per-chunk partial sums -> g_part[l][j][oc]   (fp32, 18.9 MB, L2)
// Kernel 2: two-pass: totals(+bias) -> scale/zp (warp=one l) -> fake-quant
//           re-reading partials from L1 -> out[oc][l]
// ---------------------------------------------------------------------------

#define WSTR 130  // w_s row stride (floats)

typedef unsigned long long u64;

__device__ float g_part[1024u * 36u * 128u];  // [l][j][oc]

__device__ __forceinline__ u64 fma2(u64 a, u64 b, u64 c) {
    u64 d;
    asm("fma.rn.f32x2 %0, %1, %2, %3;" : "=l"(d) : "l"(a), "l"(b), "l"(c));
    return d;
}

__device__ __forceinline__ u64 bcast2(float v) {
    u64 d;
    unsigned u = __float_as_uint(v);
    asm("mov.b64 %0, {%1, %1};" : "=l"(d) : "r"(u));
    return d;
}

__device__ __forceinline__ float2 unpack2(u64 v) {
    float2 f;
    asm("mov.b64 {%0, %1}, %2;" : "=f"(f.x), "=f"(f.y) : "l"(v));
    return f;
}

// ---------------------------------------------------------------------------
// Kernel 1: chunk partial sums.
// grid = (8 l-tiles, 36 chunks), block = 256 threads.
// Block tile: 128 oc x 128 l (4 output rows x 32 cols).
// Thread tile: 8 oc x 8 l, accumulated as 4 oc-pairs in f32x2 registers.
// ---------------------------------------------------------------------------
__global__ void __launch_bounds__(256)
k_partials(const float* __restrict__ x, const float* __restrict__ w) {
    __shared__ float x_s[5 * 6 * 34];     // [c_rel][row(6)][col(34)], zero halo
    __shared__ float w_s[32 * WSTR];      // [t][oc], padded stride

    const int j    = blockIdx.y;
    const int oh0  = blockIdx.x * 4;      // first output row of this tile
    const int base = 32 * j;              // first ckk index of this chunk
    const int cmin = base / 9;            // first channel touched (<=5 channels)
    const int tid  = threadIdx.x;

    // --- load x halo: channels cmin..cmin+4, rows oh0-1..oh0+4, cols -1..32
    for (int e = tid; e < 5 * 6 * 34; e += 256) {
        int cr  = e / 204;
        int rem = e - cr * 204;
        int rr  = rem / 34;
        int cc  = rem - rr * 34;
        int c   = cmin + cr;
        int gh  = oh0 - 1 + rr;
        int gw  = cc - 1;
        float v = 0.0f;
        if (c < 128 && (unsigned)gh < 32u && (unsigned)gw < 32u)
            v = x[(c << 10) + (gh << 5) + gw];
        x_s[e] = v;
    }
    // --- load w: w_s[m][oc] = w[oc*1152 + base + m]  (coalesced global reads)
    for (int e = tid; e < 4096; e += 256) {
        int oc = e >> 5;
        int m  = e & 31;
        w_s[m * WSTR + oc] = w[oc * 1152 + base + m];
    }
    __syncthreads();

    const int lcol = tid & 15;            // 16 l-groups of 8
    const int oc0  = (tid >> 4) << 3;     // 16 oc-groups of 8
    const int lrow = lcol >> 2;           // output row within tile (0..3)
    const int colb = (lcol & 3) << 3;     // first output col (0,8,16,24)

    u64 acc[4][8];                        // [oc-pair][l] f32x2 accumulators
#pragma unroll
    for (int p = 0; p < 4; ++p)
#pragma unroll
        for (int i = 0; i < 8; ++i) acc[p][i] = 0ull;

#pragma unroll
    for (int t = 0; t < 32; ++t) {
        const int idx = base + t;         // uniform across block
        const int c   = idx / 9;
        const int r9  = idx - c * 9;
        const int kh  = r9 / 3;
        const int kw  = r9 - kh * 3;
        const float* xr = &x_s[(c - cmin) * 204 + (lrow + kh) * 34 + colb + kw];
        const u64*   wr = (const u64*)&w_s[t * WSTR + oc0];
        const u64 w0 = wr[0], w1 = wr[1], w2 = wr[2], w3 = wr[3];
#pragma unroll
        for (int i = 0; i < 8; ++i) {
            const u64 xx = bcast2(xr[i]);
            acc[0][i] = fma2(w0, xx, acc[0][i]);
            acc[1][i] = fma2(w1, xx, acc[1][i]);
            acc[2][i] = fma2(w2, xx, acc[2][i]);
            acc[3][i] = fma2(w3, xx, acc[3][i]);
        }
    }

    // --- store partials: g_part[l][j][oc]
    float* outp = g_part + (size_t)(oh0 << 5) * 4608 + (size_t)(j << 7);
#pragma unroll
    for (int i = 0; i < 8; ++i) {
        const int l = (lcol << 3) + i;    // l within tile
        float2 a0 = unpack2(acc[0][i]);
        float2 a1 = unpack2(acc[1][i]);
        float2 a2 = unpack2(acc[2][i]);
        float2 a3 = unpack2(acc[3][i]);
        float* po = outp + (size_t)l * 4608 + oc0;
        *(float4*)(po)     = make_float4(a0.x, a0.y, a1.x, a1.y);
        *(float4*)(po + 4) = make_float4(a2.x, a2.y, a3.x, a3.y);
    }
}

// ---------------------------------------------------------------------------
// Kernel 2: two-pass fused reduce/quant. grid=128, block=256 (8 warps).
// One warp per l; lane holds 4 consecutive oc as float4 (LDG.128 streams).
// Pass 1: totals -> warp max/min -> scale/zp. Pass 2: re-read (L1) -> quant.
// ---------------------------------------------------------------------------
__global__ void __launch_bounds__(256)
k_quant(const float* __restrict__ bias, float* __restrict__ out) {
    const int tid  = threadIdx.x;
    const int lane = tid & 31;
    const int wid  = tid >> 5;
    const int l    = (blockIdx.x << 3) + wid;
    const int oc0  = lane << 2;

    const float4* bp = (const float4*)(g_part + (size_t)l * 4608) + lane;
    // j stride in float4 units: 128/4 = 32

    // --- pass 1: totals (+bias)
    float4 t4 = *(const float4*)(bias + oc0);
#pragma unroll
    for (int j = 0; j < 36; ++j) {
        float4 v = bp[j * 32];
        t4.x += v.x; t4.y += v.y; t4.z += v.z; t4.w += v.w;
    }
    float mx = fmaxf(fmaxf(t4.x, t4.y), fmaxf(t4.z, t4.w));
    float mn = fminf(fminf(t4.x, t4.y), fminf(t4.z, t4.w));
#pragma unroll
    for (int s = 16; s > 0; s >>= 1) {
        mx = fmaxf(mx, __shfl_xor_sync(0xffffffffu, mx, s));
        mn = fminf(mn, __shfl_xor_sync(0xffffffffu, mn, s));
    }

    const float sc = (mx - mn) * (1.0f / 255.0f);
    float z = -mn / sc;                              // inf/nan if sc==0
    z = fminf(fmaxf(z, 0.0f), 255.0f);               // clip (nan -> 0 via fmaxf)
    if (isnan(z)) z = 0.0f;
    const float zp  = truncf(z);                     // .int() truncation
    const float rcp = 1.0f / sc;

    // --- pass 2: fake-quant each chunk, sum (q - zp) exactly (small ints)
    float4 o = make_float4(0.f, 0.f, 0.f, 0.f);
#pragma unroll
    for (int j = 0; j < 36; ++j) {
        float4 v = bp[j * 32];
        float qx = fminf(fmaxf(rintf(v.x * rcp) + zp, 0.0f), 255.0f);
        float qy = fminf(fmaxf(rintf(v.y * rcp) + zp, 0.0f), 255.0f);
        float qz = fminf(fmaxf(rintf(v.z * rcp) + zp, 0.0f), 255.0f);
        float qw = fminf(fmaxf(rintf(v.w * rcp) + zp, 0.0f), 255.0f);
        o.x += qx - zp; o.y += qy - zp; o.z += qz - zp; o.w += qw - zp;
    }
    o.x *= sc; o.y *= sc; o.z *= sc; o.w *= sc;

    // --- transpose through smem for coalesced [oc][l] stores
    __shared__ float s[8 * 132];                     // [wid][oc], padded
    *(float4*)(s + wid * 132 + oc0) = o;
    __syncthreads();
    const int l0 = blockIdx.x << 3;
    for (int e = tid; e < 1024; e += 256) {
        int oc = e >> 3, c = e & 7;
        out[(oc << 10) + l0 + c] = s[c * 132 + oc];
    }
}

// ---------------------------------------------------------------------------
extern "C" void kernel_launch(void* const* d_in, const int* in_sizes, int n_in,
                              void* d_out, int out_size) {
    const float *x = nullptr, *w = nullptr, *b = nullptr;
    for (int i = 0; i < n_in; ++i) {
        if      (in_sizes[i] == 131072) x = (const float*)d_in[i];  // 128*32*32
        else if (in_sizes[i] == 147456) w = (const float*)d_in[i];  // 128*128*9
        else if (in_sizes[i] == 128)    b = (const float*)d_in[i];
    }
    k_partials<<<dim3(8, 36), 256>>>(x, w);
    k_quant<<<128, 256>>>(b, (float*)d_out);
}